// round 11
// baseline (speedup 1.0000x reference)
#include <cuda_runtime.h>
#include <cuda_bf16.h>
#include <stdint.h>

// ---------------- problem constants ----------------
#define N_BINS    84
#define FFTLEN    2048
#define FREQ_BINS 1025
#define HOP       512
#define T_SAMPLES 8388608
#define N_FRAMES  16381
#define CHUNKS    64          // 64 chunks x 32 base-k = 2048
#define NTL       22          // ntiles: 176 cols = 88 re/im pairs >= 84 bins
#define NBPAD     96          // bins padded (16*6)
#define KQ        11          // split-K ways for W build (11 x 3 tiles = 33)

// ---------------- device globals ----------------
__device__ __nv_bfloat16 xh_b[T_SAMPLES];          // 16 MB
__device__ __nv_bfloat16 xl_b[T_SAMPLES];          // 16 MB
// B fragments: [chunk][k16(2)][bh(2)][nt(22)][lane(32)][reg(2) u32]
__device__ __align__(128) __nv_bfloat16 Bbig[CHUNKS * 2 * 2 * NTL * 32 * 4];
// split-K partials: [kq][n(2048)][bin(96)] (wr, wi)
__device__ float2 Wpart[KQ * FFTLEN * NBPAD];      // 17.3 MB

// ---------------- f32x2 helpers (prep) ----------------
__device__ __forceinline__ uint64_t pack2(float lo, float hi) {
    uint64_t r; asm("mov.b64 %0, {%1, %2};" : "=l"(r) : "f"(lo), "f"(hi)); return r;
}
__device__ __forceinline__ uint64_t dup2(float x) {
    uint64_t r; asm("mov.b64 %0, {%1, %1};" : "=l"(r) : "f"(x)); return r;
}
__device__ __forceinline__ void unpack2(uint64_t v, float& lo, float& hi) {
    asm("mov.b64 {%0, %1}, %2;" : "=f"(lo), "=f"(hi) : "l"(v));
}
__device__ __forceinline__ void ffma2(uint64_t& acc, uint64_t a, uint64_t b) {
    asm("fma.rn.f32x2 %0, %1, %2, %0;" : "+l"(acc) : "l"(a), "l"(b));
}

// =====================================================================
// Kernel 1: merged prep.
//  CTAs [0,352): fused-W build, 4n x 6bins per thread, split-K x11.
//  CTAs [352, 352+4096): x bf16 hi/lo split (hides under W build).
// =====================================================================
__global__ void __launch_bounds__(256) prep_all(
    const float* __restrict__ x,
    const float* __restrict__ kr, const float* __restrict__ ki,
    const float* __restrict__ wcos, const float* __restrict__ wsin)
{
    __shared__ float kct[32 * NBPAD * 2];   // [kl][b][{kr,ki}] 24 KB
    __shared__ float wct[32 * 64 * 2];      // [kl][nn][{c,s}]  16 KB
    const int tid = threadIdx.x;

    if (blockIdx.x >= 352) {
        // ---------- x split ----------
        int i = ((blockIdx.x - 352) * 256 + tid) * 8;
        float4 a = *reinterpret_cast<const float4*>(x + i);
        float4 c = *reinterpret_cast<const float4*>(x + i + 4);
        float v[8] = {a.x, a.y, a.z, a.w, c.x, c.y, c.z, c.w};
#pragma unroll
        for (int j = 0; j < 4; j++) {
            __nv_bfloat16 h0 = __float2bfloat16(v[2 * j]);
            __nv_bfloat16 h1 = __float2bfloat16(v[2 * j + 1]);
            __nv_bfloat16 l0 = __float2bfloat16(v[2 * j]     - __bfloat162float(h0));
            __nv_bfloat16 l1 = __float2bfloat16(v[2 * j + 1] - __bfloat162float(h1));
            *reinterpret_cast<__nv_bfloat162*>(xh_b + i + 2 * j) = __nv_bfloat162(h0, h1);
            *reinterpret_cast<__nv_bfloat162*>(xl_b + i + 2 * j) = __nv_bfloat162(l0, l1);
        }
        return;
    }

    // ---------- fused-W build (split-K, 4n x 6b per thread) ----------
    const int n_t    = tid & 15;
    const int bin_g  = tid >> 4;                 // 0..15, 6 bins each
    const int colblk = blockIdx.x & 31;          // 32 blocks x 64 n
    const int kq     = blockIdx.x >> 5;          // 0..10
    const int n0     = colblk * 64;
    const int t0     = kq * 3;
    const int t1     = t0 + 3;                   // 11*3 = 33 tiles exactly

    uint64_t acc[4][6];
#pragma unroll
    for (int j = 0; j < 4; j++)
#pragma unroll
        for (int i = 0; i < 6; i++) acc[j][i] = 0ull;

    for (int kt = t0; kt < t1; kt++) {
        const int k0 = kt * 32;
        __syncthreads();
        for (int i = tid; i < NBPAD * 32; i += 256) {
            int b = i >> 5, kl = i & 31, kg = k0 + kl;
            float vr = 0.f, vi = 0.f;
            if (b < N_BINS && kg < FREQ_BINS) {
                vr = kr[b * FREQ_BINS + kg];
                vi = ki[b * FREQ_BINS + kg];
            }
            kct[kl * (NBPAD * 2) + b * 2]     = vr;
            kct[kl * (NBPAD * 2) + b * 2 + 1] = vi;
        }
        for (int i = tid; i < 32 * 64; i += 256) {
            int kl = i >> 6, nn = i & 63, kg = k0 + kl;
            float c = 0.f, s = 0.f;
            if (kg < FREQ_BINS) {
                c = wcos[kg * FFTLEN + n0 + nn];
                s = wsin[kg * FFTLEN + n0 + nn];
            }
            wct[kl * 128 + nn * 2]     = c;
            wct[kl * 128 + nn * 2 + 1] = s;
        }
        __syncthreads();
#pragma unroll 2
        for (int kl = 0; kl < 32; kl++) {
            const float* wp_ = &wct[kl * 128 + n_t * 2];
            uint64_t cs[4], mcs[4];
#pragma unroll
            for (int j = 0; j < 4; j++) {
                float c = wp_[j * 32], s = wp_[j * 32 + 1];
                cs[j]  = pack2(c, s);
                mcs[j] = pack2(-s, c);
            }
            const float* kp = &kct[kl * (NBPAD * 2) + bin_g * 12];
#pragma unroll
            for (int i = 0; i < 6; i++) {
                uint64_t ukr = dup2(kp[i * 2]);
                uint64_t uki = dup2(kp[i * 2 + 1]);
#pragma unroll
                for (int j = 0; j < 4; j++) {
                    ffma2(acc[j][i], ukr, cs[j]);
                    ffma2(acc[j][i], uki, mcs[j]);
                }
            }
        }
    }
#pragma unroll
    for (int j = 0; j < 4; j++) {
        const int n = n0 + n_t + j * 16;
        float2* wp = Wpart + (size_t)(kq * FFTLEN + n) * NBPAD;
#pragma unroll
        for (int i = 0; i < 6; i++) {
            int b = bin_g * 6 + i;
            float wr, wi; unpack2(acc[j][i], wr, wi);
            wp[b] = make_float2(wr, wi);
        }
    }
}

// =====================================================================
// Kernel 2: combine split-K partials -> bf16 hi/lo -> Bbig fragments.
// Each thread: one bin x 2 adjacent n (the two bytes of one frag u32).
// =====================================================================
__device__ __forceinline__ uint32_t bpack(__nv_bfloat16 a, __nv_bfloat16 b) {
    __nv_bfloat162 t(a, b);                     // a -> low half
    return *reinterpret_cast<uint32_t*>(&t);
}

__global__ void __launch_bounds__(256) combine_k(void) {
    int idx = blockIdx.x * 256 + threadIdx.x;   // over 1024 * 96
    int np = idx / NBPAD, b = idx % NBPAD;
    if (b >= N_BINS) return;
    int n0 = np * 2;
    float wr0 = 0.f, wi0 = 0.f, wr1 = 0.f, wi1 = 0.f;
#pragma unroll
    for (int q = 0; q < KQ; q++) {
        float2 v0 = Wpart[(size_t)(q * FFTLEN + n0) * NBPAD + b];
        float2 v1 = Wpart[(size_t)(q * FFTLEN + n0 + 1) * NBPAD + b];
        wr0 += v0.x; wi0 += v0.y; wr1 += v1.x; wi1 += v1.y;
    }
    __nv_bfloat16 hr0 = __float2bfloat16(wr0);
    __nv_bfloat16 lr0 = __float2bfloat16(wr0 - __bfloat162float(hr0));
    __nv_bfloat16 hw0 = __float2bfloat16(wi0);
    __nv_bfloat16 lw0 = __float2bfloat16(wi0 - __bfloat162float(hw0));
    __nv_bfloat16 hr1 = __float2bfloat16(wr1);
    __nv_bfloat16 lr1 = __float2bfloat16(wr1 - __bfloat162float(hr1));
    __nv_bfloat16 hw1 = __float2bfloat16(wi1);
    __nv_bfloat16 lw1 = __float2bfloat16(wi1 - __bfloat162float(hw1));

    uint32_t* Bu = reinterpret_cast<uint32_t*>(Bbig);
    int chunk = n0 >> 5, k16 = (n0 >> 4) & 1, kc = (n0 & 15) >> 1;
    int reg = kc >> 2;
    int base = ((chunk * 2 + k16) * 2) * NTL;
    {   // col = 2b (real part)
        int col = 2 * b;
        int lane = ((col & 7) << 2) | (kc & 3);
        int u32i = (base + (col >> 3)) * 64 + lane * 2 + reg;
        Bu[u32i] = bpack(hr0, hr1);
        Bu[u32i + NTL * 64] = bpack(lr0, lr1);
    }
    {   // col = 2b+1 (imag part)
        int col = 2 * b + 1;
        int lane = ((col & 7) << 2) | (kc & 3);
        int u32i = (base + (col >> 3)) * 64 + lane * 2 + reg;
        Bu[u32i] = bpack(hw0, hw1);
        Bu[u32i + NTL * 64] = bpack(lw0, lw1);
    }
}

// =====================================================================
// Main GEMM: CTA = 64 frames x 176 cols, 256 threads (8 warps = 2m x 2n x 2k).
// Each warp owns one k16 half (66 HMMA/chunk); cross-k partial sums merged
// through smem at the end.  2 CTAs/SM (60 KB smem each).
// =====================================================================
#define A_ST   2048                 // u32 per A stage (8 KB)
#define B_ST   (2 * 2 * NTL * 64)   // 5632 u32 (22 KB)
#define STAGE  (A_ST + B_ST)        // 7680 u32 (30 KB)
#define MM_SMEM (2 * STAGE * 4)     // 61440 bytes (>= 45056 reduction area)

__device__ __forceinline__ void mma16816(float* d, const uint32_t* a,
                                         const uint32_t* b) {
    asm volatile(
        "mma.sync.aligned.m16n8k16.row.col.f32.bf16.bf16.f32 "
        "{%0,%1,%2,%3}, {%4,%5,%6,%7}, {%8,%9}, {%0,%1,%2,%3};"
        : "+f"(d[0]), "+f"(d[1]), "+f"(d[2]), "+f"(d[3])
        : "r"(a[0]), "r"(a[1]), "r"(a[2]), "r"(a[3]), "r"(b[0]), "r"(b[1]));
}

// 256 threads: thread = (row 0..63, half 0..1, q 0..1); loads 8 u32 = its
// (row, half) A data for k16 = q.
__device__ __forceinline__ void lda(int c, int f0, int tid, uint32_t* va) {
    const int row = tid & 63, half = (tid >> 6) & 1, q = tid >> 7;
    const __nv_bfloat16* src = half ? xl_b : xh_b;
    const int g = (f0 + row) * HOP + c * 32 + q * 16;
    const uint4* p = reinterpret_cast<const uint4*>(src + g);
#pragma unroll
    for (int i = 0; i < 2; i++) {
        uint4 t = make_uint4(0u, 0u, 0u, 0u);
        if (g + i * 8 + 7 < T_SAMPLES) t = p[i];
        va[i * 4 + 0] = t.x; va[i * 4 + 1] = t.y;
        va[i * 4 + 2] = t.z; va[i * 4 + 3] = t.w;
    }
}

__device__ __forceinline__ void sts_a(const uint32_t* va, uint32_t* bufA, int tid) {
    const int row = tid & 63, half = (tid >> 6) & 1, q = tid >> 7;
    const int mtile = row >> 4;
    const int rb = (row >> 3) & 1;
    const int rl = row & 7;
#pragma unroll
    for (int kc = 0; kc < 8; kc++) {
        int ln  = (rl << 2) | (kc & 3);
        int reg = ((kc >> 2) << 1) | rb;
        int p   = (ln << 2) | reg;
        p ^= ((p >> 5) & 3) << 2;          // bank swizzle
        bufA[((q * 2 + half) * 4 + mtile) * 128 + p] = va[kc];
    }
}

__device__ __forceinline__ void ldb_async(int c, uint32_t* nbuf, int tid) {
    const char* bs = reinterpret_cast<const char*>(Bbig) + (size_t)c * (B_ST * 4);
    uint32_t bd;
    asm("{ .reg .u64 t; cvta.to.shared.u64 t, %1; cvt.u32.u64 %0, t; }"
        : "=r"(bd) : "l"((const void*)(nbuf + A_ST)));
#pragma unroll
    for (int i = 0; i < 6; i++) {
        int e = tid + i * 256;
        if (e < 1408)
            asm volatile("cp.async.ca.shared.global [%0], [%1], 16;"
                         :: "r"(bd + e * 16), "l"(bs + e * 16) : "memory");
    }
    asm volatile("cp.async.commit_group;" ::: "memory");
}

__global__ void __launch_bounds__(256, 2) cqt_mma(float* __restrict__ out) {
    extern __shared__ uint32_t sm[];
    const int tid  = threadIdx.x;
    const int lane = tid & 31, wid = tid >> 5;
    const int wm   = wid & 1, wn = (wid >> 1) & 1, wk = wid >> 2;
    const int f0   = blockIdx.x * 64;

    float acc[2][11][4];
#pragma unroll
    for (int a = 0; a < 2; a++)
#pragma unroll
        for (int b = 0; b < 11; b++)
#pragma unroll
            for (int d = 0; d < 4; d++) acc[a][b][d] = 0.f;

    uint32_t va[8];

    lda(0, f0, tid, va);
    sts_a(va, sm, tid);
    ldb_async(0, sm, tid);
    lda(1, f0, tid, va);

    for (int c = 0; c < CHUNKS; c++) {
        asm volatile("cp.async.wait_group 0;" ::: "memory");
        __syncthreads();   // A(c)+B(c) visible; compute(c-1) done by all

        if (c < CHUNKS - 1) {
            uint32_t* nbuf = sm + ((c + 1) & 1) * STAGE;
            sts_a(va, nbuf, tid);
            ldb_async(c + 1, nbuf, tid);
        }
        if (c < CHUNKS - 2) lda(c + 2, f0, tid, va);

        const uint32_t* A = sm + (c & 1) * STAGE;
        const uint32_t* B = A + A_ST;
        const int k16 = wk;
        const int psw = (lane * 4) ^ ((((lane * 4) >> 5) & 3) << 2);
        uint32_t ah[2][4], al[2][4];
#pragma unroll
        for (int mt = 0; mt < 2; mt++) {
            uint4 qh = *reinterpret_cast<const uint4*>(
                A + ((k16 * 2 + 0) * 4 + wm * 2 + mt) * 128 + psw);
            ah[mt][0] = qh.x; ah[mt][1] = qh.y; ah[mt][2] = qh.z; ah[mt][3] = qh.w;
            uint4 ql = *reinterpret_cast<const uint4*>(
                A + ((k16 * 2 + 1) * 4 + wm * 2 + mt) * 128 + psw);
            al[mt][0] = ql.x; al[mt][1] = ql.y; al[mt][2] = ql.z; al[mt][3] = ql.w;
        }
#pragma unroll
        for (int nt = 0; nt < 11; nt++) {
            int bi = ((k16 * 2) * NTL + wn * 11 + nt) * 64 + lane * 2;
            uint2 qh = *reinterpret_cast<const uint2*>(B + bi);
            uint2 ql = *reinterpret_cast<const uint2*>(B + bi + NTL * 64);
            uint32_t bh[2] = {qh.x, qh.y};
            uint32_t bl[2] = {ql.x, ql.y};
            mma16816(acc[0][nt], ah[0], bh);
            mma16816(acc[1][nt], ah[1], bh);
            mma16816(acc[0][nt], al[0], bh);
            mma16816(acc[1][nt], al[1], bh);
            mma16816(acc[0][nt], ah[0], bl);
            mma16816(acc[1][nt], ah[1], bl);
        }
    }

    // ---- cross-k reduction through smem ----
    __syncthreads();
    float4* red = reinterpret_cast<float4*>(sm);
    const int pos = (wm * 2 + wn) * 32 + lane;     // 0..127
    if (wk == 1) {
#pragma unroll
        for (int mt = 0; mt < 2; mt++)
#pragma unroll
            for (int nt = 0; nt < 11; nt++)
                red[pos * 22 + mt * 11 + nt] =
                    *reinterpret_cast<float4*>(acc[mt][nt]);
    }
    __syncthreads();
    if (wk == 0) {
#pragma unroll
        for (int mt = 0; mt < 2; mt++)
#pragma unroll
            for (int nt = 0; nt < 11; nt++) {
                float4 v = red[pos * 22 + mt * 11 + nt];
                acc[mt][nt][0] += v.x; acc[mt][nt][1] += v.y;
                acc[mt][nt][2] += v.z; acc[mt][nt][3] += v.w;
            }
        // ---- epilogue: magnitude + store ----
#pragma unroll
        for (int mt = 0; mt < 2; mt++) {
            int fr = f0 + wm * 32 + mt * 16 + (lane >> 2);
#pragma unroll
            for (int nt = 0; nt < 11; nt++) {
                int bin = wn * 44 + nt * 4 + (lane & 3);
                if (bin < N_BINS) {
                    float* d = acc[mt][nt];
                    if (fr < N_FRAMES)
                        out[bin * N_FRAMES + fr] = sqrtf(d[0] * d[0] + d[1] * d[1]);
                    if (fr + 8 < N_FRAMES)
                        out[bin * N_FRAMES + fr + 8] = sqrtf(d[2] * d[2] + d[3] * d[3]);
                }
            }
        }
    }
}

// =====================================================================
extern "C" void kernel_launch(void* const* d_in, const int* in_sizes, int n_in,
                              void* d_out, int out_size)
{
    const float* x    = (const float*)d_in[0];
    const float* wcos = (const float*)d_in[1];
    const float* wsin = (const float*)d_in[2];
    const float* kr   = (const float*)d_in[3];
    const float* ki   = (const float*)d_in[4];
    float* out = (float*)d_out;

    prep_all<<<352 + T_SAMPLES / 2048, 256>>>(x, kr, ki, wcos, wsin);
    combine_k<<<(1024 * NBPAD) / 256, 256>>>();

    cudaFuncSetAttribute(cqt_mma, cudaFuncAttributeMaxDynamicSharedMemorySize,
                         MM_SMEM);
    cqt_mma<<<16384 / 64, 256, MM_SMEM>>>(out);
}

// round 12
// speedup vs baseline: 1.1221x; 1.1221x over previous
#include <cuda_runtime.h>
#include <cuda_bf16.h>
#include <stdint.h>

// ---------------- problem constants ----------------
#define N_BINS    84
#define FFTLEN    2048
#define FREQ_BINS 1025
#define HOP       512
#define T_SAMPLES 8388608
#define N_FRAMES  16381
#define CHUNKS    64          // 64 chunks x 32 base-k = 2048
#define NTL       22          // ntiles: 176 cols = 88 re/im pairs >= 84 bins
#define NBPAD     96          // bins padded (16*6)
#define KQ        8           // split-K ways for W build
#define NCB       33          // colblks: 32 x 32 npairs + 1 for n=1024

// ---------------- device globals ----------------
__device__ __nv_bfloat16 xh_b[T_SAMPLES];          // 16 MB
__device__ __nv_bfloat16 xl_b[T_SAMPLES];          // 16 MB
// B fragments: [chunk][k16(2)][bh(2)][nt(22)][lane(32)][reg(2) u32]
__device__ __align__(128) __nv_bfloat16 Bbig[CHUNKS * 2 * 2 * NTL * 32 * 4];
// split-K partials: [kq][n(2048)][bin(96)] (wr, wi)
__device__ float2 Wpart[KQ * FFTLEN * NBPAD];      // 12.6 MB

// ---------------- f32x2 helpers (prep) ----------------
__device__ __forceinline__ uint64_t pack2(float lo, float hi) {
    uint64_t r; asm("mov.b64 %0, {%1, %2};" : "=l"(r) : "f"(lo), "f"(hi)); return r;
}
__device__ __forceinline__ uint64_t dup2(float x) {
    uint64_t r; asm("mov.b64 %0, {%1, %1};" : "=l"(r) : "f"(x)); return r;
}
__device__ __forceinline__ void unpack2(uint64_t v, float& lo, float& hi) {
    asm("mov.b64 {%0, %1}, %2;" : "=f"(lo), "=f"(hi) : "l"(v));
}
__device__ __forceinline__ void ffma2(uint64_t& acc, uint64_t a, uint64_t b) {
    asm("fma.rn.f32x2 %0, %1, %2, %0;" : "+l"(acc) : "l"(a), "l"(b));
}

// =====================================================================
// Kernel 1: merged prep.
//  CTAs [0, NCB*KQ): fused-W build with n <-> 2048-n mirror symmetry.
//    Thread: 2 npairs x 6 bins.  P,R = sum kr*(c,s); Q,S = sum ki*(s,c).
//    Wr[n]=P-Q  Wi[n]=R+S ; Wr[2048-n]=P+Q  Wi[2048-n]=S-R.
//  CTAs [NCB*KQ, +4096): x bf16 hi/lo split (hides under W build).
// =====================================================================
#define WCTAS (NCB * KQ)      // 264

__global__ void __launch_bounds__(256) prep_all(
    const float* __restrict__ x,
    const float* __restrict__ kr, const float* __restrict__ ki,
    const float* __restrict__ wcos, const float* __restrict__ wsin)
{
    __shared__ float kct[32 * NBPAD * 2];   // [kl][b][{kr,ki}] 24 KB
    __shared__ float wct[32 * 32 * 2];      // [kl][nn][{c,s}]   8 KB
    const int tid = threadIdx.x;

    if (blockIdx.x >= WCTAS) {
        // ---------- x split ----------
        int i = ((blockIdx.x - WCTAS) * 256 + tid) * 8;
        float4 a = *reinterpret_cast<const float4*>(x + i);
        float4 c = *reinterpret_cast<const float4*>(x + i + 4);
        float v[8] = {a.x, a.y, a.z, a.w, c.x, c.y, c.z, c.w};
#pragma unroll
        for (int j = 0; j < 4; j++) {
            __nv_bfloat16 h0 = __float2bfloat16(v[2 * j]);
            __nv_bfloat16 h1 = __float2bfloat16(v[2 * j + 1]);
            __nv_bfloat16 l0 = __float2bfloat16(v[2 * j]     - __bfloat162float(h0));
            __nv_bfloat16 l1 = __float2bfloat16(v[2 * j + 1] - __bfloat162float(h1));
            *reinterpret_cast<__nv_bfloat162*>(xh_b + i + 2 * j) = __nv_bfloat162(h0, h1);
            *reinterpret_cast<__nv_bfloat162*>(xl_b + i + 2 * j) = __nv_bfloat162(l0, l1);
        }
        return;
    }

    // ---------- fused-W build (split-K, mirrored n) ----------
    const int n_t    = tid & 15;
    const int bin_g  = tid >> 4;                 // 0..15, 6 bins each
    const int colblk = blockIdx.x % NCB;         // 0..32, 32 n each
    const int kq     = blockIdx.x / NCB;         // 0..7
    const int n0     = colblk * 32;
    const int t0     = kq * 4;
    const int t1     = (kq == KQ - 1) ? 33 : (t0 + 4);

    uint64_t accA[2][6], accB[2][6];
#pragma unroll
    for (int j = 0; j < 2; j++)
#pragma unroll
        for (int i = 0; i < 6; i++) { accA[j][i] = 0ull; accB[j][i] = 0ull; }

    for (int kt = t0; kt < t1; kt++) {
        const int k0 = kt * 32;
        __syncthreads();
        for (int i = tid; i < NBPAD * 32; i += 256) {
            int b = i >> 5, kl = i & 31, kg = k0 + kl;
            float vr = 0.f, vi = 0.f;
            if (b < N_BINS && kg < FREQ_BINS) {
                vr = kr[b * FREQ_BINS + kg];
                vi = ki[b * FREQ_BINS + kg];
            }
            kct[kl * (NBPAD * 2) + b * 2]     = vr;
            kct[kl * (NBPAD * 2) + b * 2 + 1] = vi;
        }
        for (int i = tid; i < 32 * 32; i += 256) {
            int kl = i >> 5, nn = i & 31, kg = k0 + kl;
            float c = 0.f, s = 0.f;
            if (kg < FREQ_BINS) {
                c = wcos[kg * FFTLEN + n0 + nn];
                s = wsin[kg * FFTLEN + n0 + nn];
            }
            wct[kl * 64 + nn * 2]     = c;
            wct[kl * 64 + nn * 2 + 1] = s;
        }
        __syncthreads();
#pragma unroll 2
        for (int kl = 0; kl < 32; kl++) {
            const float* wp_ = &wct[kl * 64 + n_t * 2];
            float c0 = wp_[0],  s0 = wp_[1];
            float c1 = wp_[32], s1 = wp_[33];
            uint64_t cs0 = pack2(c0, s0), sc0 = pack2(s0, c0);
            uint64_t cs1 = pack2(c1, s1), sc1 = pack2(s1, c1);
            const float* kp = &kct[kl * (NBPAD * 2) + bin_g * 12];
#pragma unroll
            for (int i = 0; i < 6; i++) {
                uint64_t ukr = dup2(kp[i * 2]);
                uint64_t uki = dup2(kp[i * 2 + 1]);
                ffma2(accA[0][i], ukr, cs0);
                ffma2(accB[0][i], uki, sc0);
                ffma2(accA[1][i], ukr, cs1);
                ffma2(accB[1][i], uki, sc1);
            }
        }
    }
#pragma unroll
    for (int j = 0; j < 2; j++) {
        const int n = n0 + n_t + j * 16;
        float2* wpd = Wpart + (size_t)(kq * FFTLEN + n) * NBPAD;
        float2* wpm = Wpart + (size_t)(kq * FFTLEN + (FFTLEN - n)) * NBPAD;
#pragma unroll
        for (int i = 0; i < 6; i++) {
            int b = bin_g * 6 + i;
            float P, R, Q, S;
            unpack2(accA[j][i], P, R);
            unpack2(accB[j][i], Q, S);
            if (n <= 1024)           wpd[b] = make_float2(P - Q, R + S);
            if (n >= 1 && n <= 1023) wpm[b] = make_float2(P + Q, S - R);
        }
    }
}

// =====================================================================
// Kernel 2: combine split-K partials -> bf16 hi/lo -> Bbig fragments.
// Each thread: one bin x 2 adjacent n (the two bytes of one frag u32).
// =====================================================================
__device__ __forceinline__ uint32_t bpack(__nv_bfloat16 a, __nv_bfloat16 b) {
    __nv_bfloat162 t(a, b);                     // a -> low half
    return *reinterpret_cast<uint32_t*>(&t);
}

__global__ void __launch_bounds__(256) combine_k(void) {
    int idx = blockIdx.x * 256 + threadIdx.x;   // over 1024 * 96
    int np = idx / NBPAD, b = idx % NBPAD;
    if (b >= N_BINS) return;
    int n0 = np * 2;
    float wr0 = 0.f, wi0 = 0.f, wr1 = 0.f, wi1 = 0.f;
#pragma unroll
    for (int q = 0; q < KQ; q++) {
        float2 v0 = Wpart[(size_t)(q * FFTLEN + n0) * NBPAD + b];
        float2 v1 = Wpart[(size_t)(q * FFTLEN + n0 + 1) * NBPAD + b];
        wr0 += v0.x; wi0 += v0.y; wr1 += v1.x; wi1 += v1.y;
    }
    __nv_bfloat16 hr0 = __float2bfloat16(wr0);
    __nv_bfloat16 lr0 = __float2bfloat16(wr0 - __bfloat162float(hr0));
    __nv_bfloat16 hw0 = __float2bfloat16(wi0);
    __nv_bfloat16 lw0 = __float2bfloat16(wi0 - __bfloat162float(hw0));
    __nv_bfloat16 hr1 = __float2bfloat16(wr1);
    __nv_bfloat16 lr1 = __float2bfloat16(wr1 - __bfloat162float(hr1));
    __nv_bfloat16 hw1 = __float2bfloat16(wi1);
    __nv_bfloat16 lw1 = __float2bfloat16(wi1 - __bfloat162float(hw1));

    uint32_t* Bu = reinterpret_cast<uint32_t*>(Bbig);
    int chunk = n0 >> 5, k16 = (n0 >> 4) & 1, kc = (n0 & 15) >> 1;
    int reg = kc >> 2;
    int base = ((chunk * 2 + k16) * 2) * NTL;
    {   // col = 2b (real part)
        int col = 2 * b;
        int lane = ((col & 7) << 2) | (kc & 3);
        int u32i = (base + (col >> 3)) * 64 + lane * 2 + reg;
        Bu[u32i] = bpack(hr0, hr1);
        Bu[u32i + NTL * 64] = bpack(lr0, lr1);
    }
    {   // col = 2b+1 (imag part)
        int col = 2 * b + 1;
        int lane = ((col & 7) << 2) | (kc & 3);
        int u32i = (base + (col >> 3)) * 64 + lane * 2 + reg;
        Bu[u32i] = bpack(hw0, hw1);
        Bu[u32i + NTL * 64] = bpack(lw0, lw1);
    }
}

// =====================================================================
// Main GEMM (reverted to R10-verified version): CTA = 64 frames x 176 cols,
// 128 threads (4 warps = 2m x 2n), warp tile 32 x 88, 3-product bf16 split.
// =====================================================================
#define A_ST   2048                 // u32 per A stage (8 KB)
#define B_ST   (2 * 2 * NTL * 64)   // 5632 u32 (22 KB)
#define STAGE  (A_ST + B_ST)        // 7680 u32 (30 KB)
#define MM_SMEM (2 * STAGE * 4)     // 61440 bytes

__device__ __forceinline__ void mma16816(float* d, const uint32_t* a,
                                         const uint32_t* b) {
    asm volatile(
        "mma.sync.aligned.m16n8k16.row.col.f32.bf16.bf16.f32 "
        "{%0,%1,%2,%3}, {%4,%5,%6,%7}, {%8,%9}, {%0,%1,%2,%3};"
        : "+f"(d[0]), "+f"(d[1]), "+f"(d[2]), "+f"(d[3])
        : "r"(a[0]), "r"(a[1]), "r"(a[2]), "r"(a[3]), "r"(b[0]), "r"(b[1]));
}

__device__ __forceinline__ void lda(int c, int f0, int tid, uint32_t* va) {
    const int row = tid & 63, half = tid >> 6;
    const __nv_bfloat16* src = half ? xl_b : xh_b;
    const int g = (f0 + row) * HOP + c * 32;
    const uint4* p = reinterpret_cast<const uint4*>(src + g);
#pragma unroll
    for (int i = 0; i < 4; i++) {
        uint4 t = make_uint4(0u, 0u, 0u, 0u);
        if (g + i * 8 + 7 < T_SAMPLES) t = p[i];
        va[i * 4 + 0] = t.x; va[i * 4 + 1] = t.y;
        va[i * 4 + 2] = t.z; va[i * 4 + 3] = t.w;
    }
}

__device__ __forceinline__ void sts_a(const uint32_t* va, uint32_t* bufA, int tid) {
    const int row = tid & 63, half = tid >> 6;
    const int mtile = row >> 4;
    const int rb = (row >> 3) & 1;
    const int rl = row & 7;
#pragma unroll
    for (int cp = 0; cp < 16; cp++) {
        int k16 = cp >> 3, kc = cp & 7;
        int ln  = (rl << 2) | (kc & 3);
        int reg = ((kc >> 2) << 1) | rb;
        int p   = (ln << 2) | reg;
        p ^= ((p >> 5) & 3) << 2;          // bank swizzle
        bufA[((k16 * 2 + half) * 4 + mtile) * 128 + p] = va[cp];
    }
}

__global__ void __launch_bounds__(128, 3) cqt_mma(float* __restrict__ out) {
    extern __shared__ uint32_t sm[];
    const int tid  = threadIdx.x;
    const int lane = tid & 31, wid = tid >> 5;
    const int wm   = wid & 1,  wn  = wid >> 1;
    const int f0   = blockIdx.x * 64;

    float acc[2][11][4];
#pragma unroll
    for (int a = 0; a < 2; a++)
#pragma unroll
        for (int b = 0; b < 11; b++)
#pragma unroll
            for (int d = 0; d < 4; d++) acc[a][b][d] = 0.f;

    uint32_t va[16];

    lda(0, f0, tid, va);
    sts_a(va, sm, tid);
    {
        const char* bs = reinterpret_cast<const char*>(Bbig);
        uint32_t bd;
        asm("{ .reg .u64 t; cvta.to.shared.u64 t, %1; cvt.u32.u64 %0, t; }"
            : "=r"(bd) : "l"((const void*)(sm + A_ST)));
#pragma unroll
        for (int i = 0; i < 11; i++) {
            int e = tid + i * 128;
            asm volatile("cp.async.ca.shared.global [%0], [%1], 16;"
                         :: "r"(bd + e * 16), "l"(bs + e * 16) : "memory");
        }
        asm volatile("cp.async.commit_group;" ::: "memory");
    }
    lda(1, f0, tid, va);

    for (int c = 0; c < CHUNKS; c++) {
        asm volatile("cp.async.wait_group 0;" ::: "memory");
        __syncthreads();

        if (c < CHUNKS - 1) {
            uint32_t* nbuf = sm + ((c + 1) & 1) * STAGE;
            sts_a(va, nbuf, tid);
            const char* bs = reinterpret_cast<const char*>(Bbig)
                             + (size_t)(c + 1) * (B_ST * 4);
            uint32_t bd;
            asm("{ .reg .u64 t; cvta.to.shared.u64 t, %1; cvt.u32.u64 %0, t; }"
                : "=r"(bd) : "l"((const void*)(nbuf + A_ST)));
#pragma unroll
            for (int i = 0; i < 11; i++) {
                int e = tid + i * 128;
                asm volatile("cp.async.ca.shared.global [%0], [%1], 16;"
                             :: "r"(bd + e * 16), "l"(bs + e * 16) : "memory");
            }
            asm volatile("cp.async.commit_group;" ::: "memory");
        }
        if (c < CHUNKS - 2) lda(c + 2, f0, tid, va);

        const uint32_t* A = sm + (c & 1) * STAGE;
        const uint32_t* B = A + A_ST;
#pragma unroll
        for (int k16 = 0; k16 < 2; k16++) {
            uint32_t ah[2][4], al[2][4];
            const int psw = (lane * 4) ^ ((((lane * 4) >> 5) & 3) << 2);
#pragma unroll
            for (int mt = 0; mt < 2; mt++) {
                uint4 qh = *reinterpret_cast<const uint4*>(
                    A + ((k16 * 2 + 0) * 4 + wm * 2 + mt) * 128 + psw);
                ah[mt][0] = qh.x; ah[mt][1] = qh.y; ah[mt][2] = qh.z; ah[mt][3] = qh.w;
                uint4 ql = *reinterpret_cast<const uint4*>(
                    A + ((k16 * 2 + 1) * 4 + wm * 2 + mt) * 128 + psw);
                al[mt][0] = ql.x; al[mt][1] = ql.y; al[mt][2] = ql.z; al[mt][3] = ql.w;
            }
#pragma unroll
            for (int nt = 0; nt < 11; nt++) {
                int bi = ((k16 * 2) * NTL + wn * 11 + nt) * 64 + lane * 2;
                uint2 qh = *reinterpret_cast<const uint2*>(B + bi);
                uint2 ql = *reinterpret_cast<const uint2*>(B + bi + NTL * 64);
                uint32_t bh[2] = {qh.x, qh.y};
                uint32_t bl[2] = {ql.x, ql.y};
                mma16816(acc[0][nt], ah[0], bh);
                mma16816(acc[1][nt], ah[1], bh);
                mma16816(acc[0][nt], al[0], bh);
                mma16816(acc[1][nt], al[1], bh);
                mma16816(acc[0][nt], ah[0], bl);
                mma16816(acc[1][nt], ah[1], bl);
            }
        }
    }

    // ---- epilogue: magnitude + store ----
#pragma unroll
    for (int mt = 0; mt < 2; mt++) {
        int fr = f0 + wm * 32 + mt * 16 + (lane >> 2);
#pragma unroll
        for (int nt = 0; nt < 11; nt++) {
            int bin = wn * 44 + nt * 4 + (lane & 3);
            if (bin < N_BINS) {
                float* d = acc[mt][nt];
                if (fr < N_FRAMES)
                    out[bin * N_FRAMES + fr] = sqrtf(d[0] * d[0] + d[1] * d[1]);
                if (fr + 8 < N_FRAMES)
                    out[bin * N_FRAMES + fr + 8] = sqrtf(d[2] * d[2] + d[3] * d[3]);
            }
        }
    }
}

// =====================================================================
extern "C" void kernel_launch(void* const* d_in, const int* in_sizes, int n_in,
                              void* d_out, int out_size)
{
    const float* x    = (const float*)d_in[0];
    const float* wcos = (const float*)d_in[1];
    const float* wsin = (const float*)d_in[2];
    const float* kr   = (const float*)d_in[3];
    const float* ki   = (const float*)d_in[4];
    float* out = (float*)d_out;

    prep_all<<<WCTAS + T_SAMPLES / 2048, 256>>>(x, kr, ki, wcos, wsin);
    combine_k<<<(1024 * NBPAD) / 256, 256>>>();

    cudaFuncSetAttribute(cqt_mma, cudaFuncAttributeMaxDynamicSharedMemorySize,
                         MM_SMEM);
    cqt_mma<<<16384 / 64, 128, MM_SMEM>>>(out);
}

// round 13
// speedup vs baseline: 1.1655x; 1.0387x over previous
#include <cuda_runtime.h>
#include <cuda_bf16.h>
#include <stdint.h>

// ---------------- problem constants ----------------
#define N_BINS    84
#define FFTLEN    2048
#define FREQ_BINS 1025
#define HOP       512
#define T_SAMPLES 8388608
#define N_FRAMES  16381
#define CHUNKS    64          // 64 chunks x 32 base-k = 2048
#define NTL       22          // ntiles: 176 cols = 88 re/im pairs >= 84 bins
#define NBPAD     96          // bins padded (16*6)
#define KQ        8           // split-K ways for W build
#define NCB       22          // colblks: 22 x 48 n covers [0,1055] >= [0,1024]

// ---------------- device globals ----------------
__device__ __nv_bfloat16 xh_b[T_SAMPLES];          // 16 MB
__device__ __nv_bfloat16 xl_b[T_SAMPLES];          // 16 MB
// B fragments, FUSED hi/lo: [chunk][k16(2)][nt(22)][lane(32)][bh0,bh1,bl0,bl1]
__device__ __align__(128) __nv_bfloat16 Bbig[CHUNKS * 2 * NTL * 32 * 8];
// split-K partials: [kq][n(2048)][bin(96)] (wr, wi)
__device__ float2 Wpart[KQ * FFTLEN * NBPAD];      // 12.6 MB

// ---------------- f32x2 helpers (prep) ----------------
__device__ __forceinline__ uint64_t pack2(float lo, float hi) {
    uint64_t r; asm("mov.b64 %0, {%1, %2};" : "=l"(r) : "f"(lo), "f"(hi)); return r;
}
__device__ __forceinline__ uint64_t dup2(float x) {
    uint64_t r; asm("mov.b64 %0, {%1, %1};" : "=l"(r) : "f"(x)); return r;
}
__device__ __forceinline__ void unpack2(uint64_t v, float& lo, float& hi) {
    asm("mov.b64 {%0, %1}, %2;" : "=f"(lo), "=f"(hi) : "l"(v));
}
__device__ __forceinline__ void ffma2(uint64_t& acc, uint64_t a, uint64_t b) {
    asm("fma.rn.f32x2 %0, %1, %2, %0;" : "+l"(acc) : "l"(a), "l"(b));
}

// =====================================================================
// Kernel 1: merged prep.
//  CTAs [0, NCB*KQ): fused-W build with n <-> 2048-n mirror symmetry.
//    Thread: 3 n x 6 bins (b = bin_g + 16*i, conflict-free kct banks).
//    P,R = sum kr*(c,s); Q,S = sum ki*(s,c).
//    Wr[n]=P-Q  Wi[n]=R+S ; Wr[2048-n]=P+Q  Wi[2048-n]=S-R.
//  CTAs [NCB*KQ, +4096): x bf16 hi/lo split (hides under W build).
// =====================================================================
#define WCTAS (NCB * KQ)      // 176

__global__ void __launch_bounds__(256) prep_all(
    const float* __restrict__ x,
    const float* __restrict__ kr, const float* __restrict__ ki,
    const float* __restrict__ wcos, const float* __restrict__ wsin)
{
    __shared__ float kct[32 * NBPAD * 2];   // [kl][b][{kr,ki}] 24 KB
    __shared__ float wct[32 * 48 * 2];      // [kl][nn][{c,s}]  12 KB
    const int tid = threadIdx.x;

    if (blockIdx.x >= WCTAS) {
        // ---------- x split ----------
        int i = ((blockIdx.x - WCTAS) * 256 + tid) * 8;
        float4 a = *reinterpret_cast<const float4*>(x + i);
        float4 c = *reinterpret_cast<const float4*>(x + i + 4);
        float v[8] = {a.x, a.y, a.z, a.w, c.x, c.y, c.z, c.w};
#pragma unroll
        for (int j = 0; j < 4; j++) {
            __nv_bfloat16 h0 = __float2bfloat16(v[2 * j]);
            __nv_bfloat16 h1 = __float2bfloat16(v[2 * j + 1]);
            __nv_bfloat16 l0 = __float2bfloat16(v[2 * j]     - __bfloat162float(h0));
            __nv_bfloat16 l1 = __float2bfloat16(v[2 * j + 1] - __bfloat162float(h1));
            *reinterpret_cast<__nv_bfloat162*>(xh_b + i + 2 * j) = __nv_bfloat162(h0, h1);
            *reinterpret_cast<__nv_bfloat162*>(xl_b + i + 2 * j) = __nv_bfloat162(l0, l1);
        }
        return;
    }

    // ---------- fused-W build (split-K, mirrored n, 3n x 6b) ----------
    const int n_t    = tid & 15;
    const int bin_g  = tid >> 4;                 // 0..15
    const int colblk = blockIdx.x % NCB;         // 0..21, 48 n each
    const int kq     = blockIdx.x / NCB;         // 0..7
    const int n0     = colblk * 48;
    const int t0     = kq * 4;
    const int t1     = (kq == KQ - 1) ? 33 : (t0 + 4);

    uint64_t accA[3][6], accB[3][6];
#pragma unroll
    for (int j = 0; j < 3; j++)
#pragma unroll
        for (int i = 0; i < 6; i++) { accA[j][i] = 0ull; accB[j][i] = 0ull; }

    for (int kt = t0; kt < t1; kt++) {
        const int k0 = kt * 32;
        __syncthreads();
        for (int i = tid; i < NBPAD * 32; i += 256) {
            int b = i >> 5, kl = i & 31, kg = k0 + kl;
            float vr = 0.f, vi = 0.f;
            if (b < N_BINS && kg < FREQ_BINS) {
                vr = kr[b * FREQ_BINS + kg];
                vi = ki[b * FREQ_BINS + kg];
            }
            kct[kl * (NBPAD * 2) + b * 2]     = vr;
            kct[kl * (NBPAD * 2) + b * 2 + 1] = vi;
        }
        for (int q = 0; q < 6; q++) {
            int i = tid + q * 256;               // 0..1535 = 32*48
            int kl = i / 48, nn = i % 48, kg = k0 + kl;
            float c = 0.f, s = 0.f;
            if (kg < FREQ_BINS) {
                c = wcos[kg * FFTLEN + n0 + nn];
                s = wsin[kg * FFTLEN + n0 + nn];
            }
            wct[kl * 96 + nn * 2]     = c;
            wct[kl * 96 + nn * 2 + 1] = s;
        }
        __syncthreads();
#pragma unroll 2
        for (int kl = 0; kl < 32; kl++) {
            const float* wp_ = &wct[kl * 96 + n_t * 2];
            uint64_t cs[3], sc[3];
#pragma unroll
            for (int j = 0; j < 3; j++) {
                float c = wp_[j * 32], s = wp_[j * 32 + 1];  // nn = n_t + 16j
                cs[j] = pack2(c, s);
                sc[j] = pack2(s, c);
            }
            const float* kp = &kct[kl * (NBPAD * 2) + bin_g * 2];
#pragma unroll
            for (int i = 0; i < 6; i++) {
                uint64_t ukr = dup2(kp[i * 32]);         // b = bin_g + 16i
                uint64_t uki = dup2(kp[i * 32 + 1]);
#pragma unroll
                for (int j = 0; j < 3; j++) {
                    ffma2(accA[j][i], ukr, cs[j]);
                    ffma2(accB[j][i], uki, sc[j]);
                }
            }
        }
    }
#pragma unroll
    for (int j = 0; j < 3; j++) {
        const int n = n0 + n_t + j * 16;
        float2* wpd = Wpart + (size_t)(kq * FFTLEN + n) * NBPAD;
        float2* wpm = Wpart + (size_t)(kq * FFTLEN + (FFTLEN - n)) * NBPAD;
#pragma unroll
        for (int i = 0; i < 6; i++) {
            int b = bin_g + 16 * i;
            if (b >= N_BINS) continue;
            float P, R, Q, S;
            unpack2(accA[j][i], P, R);
            unpack2(accB[j][i], Q, S);
            if (n <= 1024)           wpd[b] = make_float2(P - Q, R + S);
            if (n >= 1 && n <= 1023) wpm[b] = make_float2(P + Q, S - R);
        }
    }
}

// =====================================================================
// Kernel 2: combine split-K partials -> bf16 hi/lo -> Bbig fragments.
// Each thread: one bin x 2 adjacent n (the two bytes of one frag u32).
// Fused layout: [chunk][k16][nt][lane][bh0,bh1,bl0,bl1] u32.
// =====================================================================
__device__ __forceinline__ uint32_t bpack(__nv_bfloat16 a, __nv_bfloat16 b) {
    __nv_bfloat162 t(a, b);                     // a -> low half
    return *reinterpret_cast<uint32_t*>(&t);
}

__global__ void __launch_bounds__(256) combine_k(void) {
    int idx = blockIdx.x * 256 + threadIdx.x;   // over 1024 * 96
    int np = idx / NBPAD, b = idx % NBPAD;
    if (b >= N_BINS) return;
    int n0 = np * 2;
    float wr0 = 0.f, wi0 = 0.f, wr1 = 0.f, wi1 = 0.f;
#pragma unroll
    for (int q = 0; q < KQ; q++) {
        float2 v0 = Wpart[(size_t)(q * FFTLEN + n0) * NBPAD + b];
        float2 v1 = Wpart[(size_t)(q * FFTLEN + n0 + 1) * NBPAD + b];
        wr0 += v0.x; wi0 += v0.y; wr1 += v1.x; wi1 += v1.y;
    }
    __nv_bfloat16 hr0 = __float2bfloat16(wr0);
    __nv_bfloat16 lr0 = __float2bfloat16(wr0 - __bfloat162float(hr0));
    __nv_bfloat16 hw0 = __float2bfloat16(wi0);
    __nv_bfloat16 lw0 = __float2bfloat16(wi0 - __bfloat162float(hw0));
    __nv_bfloat16 hr1 = __float2bfloat16(wr1);
    __nv_bfloat16 lr1 = __float2bfloat16(wr1 - __bfloat162float(hr1));
    __nv_bfloat16 hw1 = __float2bfloat16(wi1);
    __nv_bfloat16 lw1 = __float2bfloat16(wi1 - __bfloat162float(hw1));

    uint32_t* Bu = reinterpret_cast<uint32_t*>(Bbig);
    int chunk = n0 >> 5, k16 = (n0 >> 4) & 1, kc = (n0 & 15) >> 1;
    int reg = kc >> 2;
    int base = (chunk * 2 + k16) * NTL;
    {   // col = 2b (real part)
        int col = 2 * b;
        int lane = ((col & 7) << 2) | (kc & 3);
        int u32i = (base + (col >> 3)) * 128 + lane * 4 + reg;
        Bu[u32i]     = bpack(hr0, hr1);
        Bu[u32i + 2] = bpack(lr0, lr1);
    }
    {   // col = 2b+1 (imag part)
        int col = 2 * b + 1;
        int lane = ((col & 7) << 2) | (kc & 3);
        int u32i = (base + (col >> 3)) * 128 + lane * 4 + reg;
        Bu[u32i]     = bpack(hw0, hw1);
        Bu[u32i + 2] = bpack(lw0, lw1);
    }
}

// =====================================================================
// Main GEMM: CTA = 64 frames x 176 cols, 128 threads (4 warps = 2m x 2n),
// warp tile 32 x 88, 3-product bf16 split.  B frags read as one LDS.128.
// =====================================================================
#define A_ST   2048                 // u32 per A stage (8 KB)
#define B_ST   (2 * NTL * 128)      // 5632 u32 (22 KB)
#define STAGE  (A_ST + B_ST)        // 7680 u32 (30 KB)
#define MM_SMEM (2 * STAGE * 4)     // 61440 bytes

__device__ __forceinline__ void mma16816(float* d, const uint32_t* a,
                                         const uint32_t* b) {
    asm volatile(
        "mma.sync.aligned.m16n8k16.row.col.f32.bf16.bf16.f32 "
        "{%0,%1,%2,%3}, {%4,%5,%6,%7}, {%8,%9}, {%0,%1,%2,%3};"
        : "+f"(d[0]), "+f"(d[1]), "+f"(d[2]), "+f"(d[3])
        : "r"(a[0]), "r"(a[1]), "r"(a[2]), "r"(a[3]), "r"(b[0]), "r"(b[1]));
}

__device__ __forceinline__ void lda(int c, int f0, int tid, uint32_t* va) {
    const int row = tid & 63, half = tid >> 6;
    const __nv_bfloat16* src = half ? xl_b : xh_b;
    const int g = (f0 + row) * HOP + c * 32;
    const uint4* p = reinterpret_cast<const uint4*>(src + g);
#pragma unroll
    for (int i = 0; i < 4; i++) {
        uint4 t = make_uint4(0u, 0u, 0u, 0u);
        if (g + i * 8 + 7 < T_SAMPLES) t = p[i];
        va[i * 4 + 0] = t.x; va[i * 4 + 1] = t.y;
        va[i * 4 + 2] = t.z; va[i * 4 + 3] = t.w;
    }
}

__device__ __forceinline__ void sts_a(const uint32_t* va, uint32_t* bufA, int tid) {
    const int row = tid & 63, half = tid >> 6;
    const int mtile = row >> 4;
    const int rb = (row >> 3) & 1;
    const int rl = row & 7;
#pragma unroll
    for (int cp = 0; cp < 16; cp++) {
        int k16 = cp >> 3, kc = cp & 7;
        int ln  = (rl << 2) | (kc & 3);
        int reg = ((kc >> 2) << 1) | rb;
        int p   = (ln << 2) | reg;
        p ^= ((p >> 5) & 3) << 2;          // bank swizzle
        bufA[((k16 * 2 + half) * 4 + mtile) * 128 + p] = va[cp];
    }
}

__global__ void __launch_bounds__(128, 3) cqt_mma(float* __restrict__ out) {
    extern __shared__ uint32_t sm[];
    const int tid  = threadIdx.x;
    const int lane = tid & 31, wid = tid >> 5;
    const int wm   = wid & 1,  wn  = wid >> 1;
    const int f0   = blockIdx.x * 64;

    float acc[2][11][4];
#pragma unroll
    for (int a = 0; a < 2; a++)
#pragma unroll
        for (int b = 0; b < 11; b++)
#pragma unroll
            for (int d = 0; d < 4; d++) acc[a][b][d] = 0.f;

    uint32_t va[16];

    lda(0, f0, tid, va);
    sts_a(va, sm, tid);
    {
        const char* bs = reinterpret_cast<const char*>(Bbig);
        uint32_t bd;
        asm("{ .reg .u64 t; cvta.to.shared.u64 t, %1; cvt.u32.u64 %0, t; }"
            : "=r"(bd) : "l"((const void*)(sm + A_ST)));
#pragma unroll
        for (int i = 0; i < 11; i++) {
            int e = tid + i * 128;
            asm volatile("cp.async.ca.shared.global [%0], [%1], 16;"
                         :: "r"(bd + e * 16), "l"(bs + e * 16) : "memory");
        }
        asm volatile("cp.async.commit_group;" ::: "memory");
    }
    lda(1, f0, tid, va);

    for (int c = 0; c < CHUNKS; c++) {
        asm volatile("cp.async.wait_group 0;" ::: "memory");
        __syncthreads();

        if (c < CHUNKS - 1) {
            uint32_t* nbuf = sm + ((c + 1) & 1) * STAGE;
            sts_a(va, nbuf, tid);
            const char* bs = reinterpret_cast<const char*>(Bbig)
                             + (size_t)(c + 1) * (B_ST * 4);
            uint32_t bd;
            asm("{ .reg .u64 t; cvta.to.shared.u64 t, %1; cvt.u32.u64 %0, t; }"
                : "=r"(bd) : "l"((const void*)(nbuf + A_ST)));
#pragma unroll
            for (int i = 0; i < 11; i++) {
                int e = tid + i * 128;
                asm volatile("cp.async.ca.shared.global [%0], [%1], 16;"
                             :: "r"(bd + e * 16), "l"(bs + e * 16) : "memory");
            }
            asm volatile("cp.async.commit_group;" ::: "memory");
        }
        if (c < CHUNKS - 2) lda(c + 2, f0, tid, va);

        const uint32_t* A = sm + (c & 1) * STAGE;
        const uint32_t* B = A + A_ST;
#pragma unroll
        for (int k16 = 0; k16 < 2; k16++) {
            uint32_t ah[2][4], al[2][4];
            const int psw = (lane * 4) ^ ((((lane * 4) >> 5) & 3) << 2);
#pragma unroll
            for (int mt = 0; mt < 2; mt++) {
                uint4 qh = *reinterpret_cast<const uint4*>(
                    A + ((k16 * 2 + 0) * 4 + wm * 2 + mt) * 128 + psw);
                ah[mt][0] = qh.x; ah[mt][1] = qh.y; ah[mt][2] = qh.z; ah[mt][3] = qh.w;
                uint4 ql = *reinterpret_cast<const uint4*>(
                    A + ((k16 * 2 + 1) * 4 + wm * 2 + mt) * 128 + psw);
                al[mt][0] = ql.x; al[mt][1] = ql.y; al[mt][2] = ql.z; al[mt][3] = ql.w;
            }
#pragma unroll
            for (int nt = 0; nt < 11; nt++) {
                int bi = (k16 * NTL + wn * 11 + nt) * 128 + lane * 4;
                uint4 q = *reinterpret_cast<const uint4*>(B + bi);
                uint32_t bh[2] = {q.x, q.y};
                uint32_t bl[2] = {q.z, q.w};
                mma16816(acc[0][nt], ah[0], bh);
                mma16816(acc[1][nt], ah[1], bh);
                mma16816(acc[0][nt], al[0], bh);
                mma16816(acc[1][nt], al[1], bh);
                mma16816(acc[0][nt], ah[0], bl);
                mma16816(acc[1][nt], ah[1], bl);
            }
        }
    }

    // ---- epilogue: magnitude + store ----
#pragma unroll
    for (int mt = 0; mt < 2; mt++) {
        int fr = f0 + wm * 32 + mt * 16 + (lane >> 2);
#pragma unroll
        for (int nt = 0; nt < 11; nt++) {
            int bin = wn * 44 + nt * 4 + (lane & 3);
            if (bin < N_BINS) {
                float* d = acc[mt][nt];
                if (fr < N_FRAMES)
                    out[bin * N_FRAMES + fr] = sqrtf(d[0] * d[0] + d[1] * d[1]);
                if (fr + 8 < N_FRAMES)
                    out[bin * N_FRAMES + fr + 8] = sqrtf(d[2] * d[2] + d[3] * d[3]);
            }
        }
    }
}

// =====================================================================
extern "C" void kernel_launch(void* const* d_in, const int* in_sizes, int n_in,
                              void* d_out, int out_size)
{
    const float* x    = (const float*)d_in[0];
    const float* wcos = (const float*)d_in[1];
    const float* wsin = (const float*)d_in[2];
    const float* kr   = (const float*)d_in[3];
    const float* ki   = (const float*)d_in[4];
    float* out = (float*)d_out;

    prep_all<<<WCTAS + T_SAMPLES / 2048, 256>>>(x, kr, ki, wcos, wsin);
    combine_k<<<(1024 * NBPAD) / 256, 256>>>();

    cudaFuncSetAttribute(cqt_mma, cudaFuncAttributeMaxDynamicSharedMemorySize,
                         MM_SMEM);
    cqt_mma<<<16384 / 64, 128, MM_SMEM>>>(out);
}